// round 8
// baseline (speedup 1.0000x reference)
#include <cuda_runtime.h>
#include <cuda_fp16.h>
#include <cstdint>

// Problem constants
#define D_IN   256
#define D_OUT  256
#define BATCH  512
#define KNOTS  64
#define INV_H  15.75f          // 63/4, exact in fp32
#define H_VAL  (4.0f/63.0f)

#define NCHUNK 32              // din chunks
#define DCHUNK 8               // din per chunk
#define TB     256             // batch rows per block

// B tile: 64 knots x 32 pairs of uint4 {y2(p), hm2(p), y2(p+32), hm2(p+32)} = 32KB
#define TILE_U4 (64*32)        // 2048 uint4

// B smem: 2 tiles (64KB) + cw (2048 uint4 = 32KB) = 96KB
#define SMEM_BYTES ((2*TILE_U4 + 2048)*16)

// Scratch (device globals; no allocation)
__device__ uint4 g_pack2[(size_t)D_IN * 4 * TILE_U4];           // 33.5 MB
__device__ float g_partial[(size_t)NCHUNK * BATCH * D_OUT];     // 16 MB

// ---------------------------------------------------------------------------
// PCHIP helpers (branch-free)
// ---------------------------------------------------------------------------
__device__ __forceinline__ float pchip_interior(float d0, float d1) {
    float p   = d0 * d1;
    float den = d0 + d1;
    float m   = __fdividef(2.0f * p, den);
    bool  ok  = (p > 0.0f) && (fabsf(den) >= 1e-12f);
    return ok ? m : 0.0f;
}
__device__ __forceinline__ float pchip_endpoint(float d_near, float d_far) {
    float m = 1.5f * d_near - 0.5f * d_far;
    m = (m * d_near <= 0.0f) ? 0.0f : m;
    bool clamp3 = (d_near * d_far < 0.0f) && (fabsf(m) > 3.0f * fabsf(d_near));
    return clamp3 ? 3.0f * d_near : m;
}

// 4 records (knots jb..jb+3) for one spline. rowd points at y[jb] in smem
// (data at offset +1 within a 69-float pitch row, so rowd[-1] is valid: pad
// slot for jb==0, else y[jb-1]).
__device__ __forceinline__ void spline4(const float* __restrict__ rowd, int jb,
                                        unsigned y2[4], unsigned h2[4]) {
    float ly[7];
#pragma unroll
    for (int k = 0; k < 7; ++k) ly[k] = rowd[k - 1];   // y[jb-1 .. jb+5]

    float d[6];
#pragma unroll
    for (int k = 0; k < 6; ++k) d[k] = (ly[k + 1] - ly[k]) * INV_H;

    float s[5];
#pragma unroll
    for (int k = 0; k < 5; ++k) s[k] = pchip_interior(d[k], d[k + 1]);
    if (jb == 0)  s[0] = pchip_endpoint(d[1], d[2]);   // m0
    if (jb == 60) s[3] = pchip_endpoint(d[3], d[2]);   // m63 (record 63 never gathered)

#pragma unroll
    for (int kk = 0; kk < 4; ++kk) {
        __half2 yv = __floats2half2_rn(ly[kk + 1], ly[kk + 2]);
        __half2 hv = __floats2half2_rn(H_VAL * s[kk], H_VAL * s[kk + 1]);
        y2[kk] = *reinterpret_cast<unsigned*>(&yv);
        h2[kk] = *reinterpret_cast<unsigned*>(&hv);
    }
}

// ---------------------------------------------------------------------------
// Kernel A: PCHIP + pack. Grid = 1024 groups x 2 halves, 256 threads.
// Block (bx, ph) handles pairs p = ph*16+i (i<16), i.e. splines p and p+32 of
// dout-group bx. Thread (i = t&15, q = t>>4) computes records jb=4q..4q+3 for
// its spline pair. Staging pitch 69 -> conflict-free window reads.
// ---------------------------------------------------------------------------
__global__ void __launch_bounds__(256) pchip_pack_kernel(const float* __restrict__ y) {
    __shared__ float sy[32 * 69];                  // [staged row][1 + knot]

    const int t  = threadIdx.x;
    const int bx = blockIdx.x >> 1;                // din*4 + dxt
    const int ph = blockIdx.x & 1;                 // pair half

    // stage 8KB: 32 rows x 64 knots; staged row r<16 -> spline ph*16+r,
    // r>=16 -> spline ph*16+(r-16)+32.
    const float* src = y + (size_t)bx * 4096;
#pragma unroll
    for (int f = t; f < 512; f += 256) {           // float4 index
        int r    = f >> 4;
        int col  = (f & 15) << 2;
        int spl  = ph * 16 + ((r < 16) ? r : (r + 16));
        float4 v = *(const float4*)(src + spl * KNOTS + col);
        float* dp = sy + r * 69 + 1 + col;
        dp[0] = v.x; dp[1] = v.y; dp[2] = v.z; dp[3] = v.w;
    }
    __syncthreads();

    const int i  = t & 15;
    const int q  = t >> 4;
    const int jb = q << 2;                         // 0..60

    unsigned ya[4], hA[4], yb[4], hB[4];
    spline4(sy + i * 69 + 1 + jb,        jb, ya, hA);   // spline ph*16+i
    spline4(sy + (i + 16) * 69 + 1 + jb, jb, yb, hB);   // spline ph*16+i+32

    uint4* dst = g_pack2 + (size_t)bx * TILE_U4 + jb * 32 + (ph * 16 + i);
#pragma unroll
    for (int kk = 0; kk < 4; ++kk) {
        uint4 rec;
        rec.x = ya[kk]; rec.y = hA[kk]; rec.z = yb[kk]; rec.w = hB[kk];
        dst[kk * 32] = rec;
    }
}

// ---------------------------------------------------------------------------
// Kernel B: main gather-accumulate.
// Grid (4 dxt, 2 by, 32 ch) = 256 blocks, 512 threads, 2 blocks/SM (32 warps).
// Warp w (of 16) owns b rows [w*16, w*16+16); lane l owns douts l and l+32.
// Per (b,din): broadcast LDS.128 {wy,wh,byteoff} + one gather LDS.128.
// ---------------------------------------------------------------------------
__device__ __forceinline__ void cp_async16(void* dst, const void* src) {
    unsigned sa = (unsigned)__cvta_generic_to_shared(dst);
    asm volatile("cp.async.cg.shared.global [%0], [%1], 16;\n" :: "r"(sa), "l"(src));
}
__device__ __forceinline__ __half2 u2h(unsigned u) {
    return *reinterpret_cast<__half2*>(&u);
}

__global__ void __launch_bounds__(512, 2) kan_main_kernel(const float* __restrict__ x) {
    extern __shared__ uint4 sm4[];
    uint4* tile = sm4;                       // 2 x TILE_U4
    uint4* cw   = sm4 + 2 * TILE_U4;         // 2048: {wy, wh, byteoff, 0}

    const int dx  = blockIdx.x;   // dout tile of 64 (0..3)
    const int by  = blockIdx.y;   // b tile (0..1)
    const int ch  = blockIdx.z;   // din chunk (0..31)
    const int tid = threadIdx.x;

    // ---- hermite weights + gather byte offset ----
    for (int i = tid; i < TB * DCHUNK; i += 512) {
        int bb = i >> 3, dl = i & 7;
        float xv = x[(by * TB + bb) * D_IN + ch * DCHUNK + dl];
        xv = fminf(fmaxf(xv, -2.0f), 2.0f);
        float tt = (xv + 2.0f) * INV_H;
        int idx = (int)floorf(tt);
        if (idx > KNOTS - 2) idx = KNOTS - 2;
        if (idx < 0) idx = 0;
        float u  = tt - (float)idx;
        float u2 = u * u, u3 = u2 * u;
        float h00 = 2.0f * u3 - 3.0f * u2 + 1.0f;
        float h10 = u3 - 2.0f * u2 + u;
        float h01 = 3.0f * u2 - 2.0f * u3;
        float h11 = u3 - u2;
        __half2 wy = __floats2half2_rn(h00, h01);
        __half2 wh = __floats2half2_rn(h10, h11);
        uint4 r;
        r.x = *reinterpret_cast<unsigned*>(&wy);
        r.y = *reinterpret_cast<unsigned*>(&wh);
        r.z = (unsigned)(idx << 9);          // idx * 512B (row = 32 uint4)
        r.w = 0;
        cw[i] = r;
    }

    const int w = tid >> 5, l = tid & 31;    // 16 warps
    float acc0[16], acc1[16];
#pragma unroll
    for (int bb = 0; bb < 16; ++bb) { acc0[bb] = 0.0f; acc1[bb] = 0.0f; }

    auto issue_copy = [&](int d, int st) {
        const uint4* src = g_pack2 + ((size_t)(ch * DCHUNK + d) * 4 + dx) * TILE_U4;
        uint4* dst = tile + st * TILE_U4;
#pragma unroll
        for (int j = tid; j < TILE_U4; j += 512) cp_async16(dst + j, src + j);
    };

    issue_copy(0, 0);
    asm volatile("cp.async.commit_group;\n" ::: "memory");

    for (int d = 0; d < DCHUNK; ++d) {
        const int st = d & 1;
        if (d < DCHUNK - 1) {
            issue_copy(d + 1, st ^ 1);
            asm volatile("cp.async.commit_group;\n" ::: "memory");
            asm volatile("cp.async.wait_group 1;\n" ::: "memory");
        } else {
            asm volatile("cp.async.wait_group 0;\n" ::: "memory");
        }
        __syncthreads();

        const char* tb = (const char*)(tile + st * TILE_U4) + (l << 4);
        const int base = (w * 16) * DCHUNK + d;

#pragma unroll 8
        for (int bb = 0; bb < 16; ++bb) {
            uint4 r = cw[base + bb * DCHUNK];              // broadcast LDS.128
            uint4 g = *(const uint4*)(tb + r.z);           // gather LDS.128

            __half2 p0 = __hfma2(u2h(r.y), u2h(g.y), __hmul2(u2h(r.x), u2h(g.x)));
            __half2 p1 = __hfma2(u2h(r.y), u2h(g.w), __hmul2(u2h(r.x), u2h(g.z)));

            acc0[bb] += __half2float(__hadd(__low2half(p0), __high2half(p0)));
            acc1[bb] += __half2float(__hadd(__low2half(p1), __high2half(p1)));
        }
        __syncthreads();
    }

    // ---- write partials ----
    float* P = g_partial + ((size_t)ch * BATCH + by * TB + w * 16) * D_OUT + dx * 64;
#pragma unroll
    for (int bb = 0; bb < 16; ++bb) {
        P[bb * D_OUT + l]      = acc0[bb];
        P[bb * D_OUT + l + 32] = acc1[bb];
    }
}

// ---------------------------------------------------------------------------
// Kernel C: reduce 32 partials + bias
// ---------------------------------------------------------------------------
__global__ void __launch_bounds__(256) reduce_kernel(
        const float* __restrict__ bias, float* __restrict__ out) {
    int i = blockIdx.x * 256 + threadIdx.x;            // float4 index
    const float4* P = (const float4*)g_partial;
    float4 s = ((const float4*)bias)[i & 63];
#pragma unroll
    for (int c = 0; c < NCHUNK; ++c) {
        float4 p = P[(size_t)c * (BATCH * D_OUT / 4) + i];
        s.x += p.x; s.y += p.y; s.z += p.z; s.w += p.w;
    }
    ((float4*)out)[i] = s;
}

// ---------------------------------------------------------------------------
extern "C" void kernel_launch(void* const* d_in, const int* in_sizes, int n_in,
                              void* d_out, int out_size) {
    const float* x    = (const float*)d_in[0];
    const float* y    = (const float*)d_in[1];
    const float* bias = (const float*)d_in[2];
    float* out = (float*)d_out;

    cudaFuncSetAttribute(kan_main_kernel,
                         cudaFuncAttributeMaxDynamicSharedMemorySize, SMEM_BYTES);

    pchip_pack_kernel<<<D_IN * 4 * 2, 256>>>(y);
    kan_main_kernel<<<dim3(4, 2, NCHUNK), 512, SMEM_BYTES>>>(x);
    reduce_kernel<<<(BATCH * D_OUT / 4) / 256, 256>>>(bias, out);
}

// round 9
// speedup vs baseline: 1.6776x; 1.6776x over previous
#include <cuda_runtime.h>
#include <cuda_fp16.h>
#include <cstdint>

// Problem constants
#define D_IN   256
#define D_OUT  256
#define BATCH  512
#define KNOTS  64
#define INV_H  15.75f          // 63/4, exact in fp32
#define H_VAL  (4.0f/63.0f)

#define NCHUNK 32              // din chunks
#define DCHUNK 8               // din per chunk
#define TB     256             // batch rows per block

// B tile: 64 knots x 32 pairs of uint4 {y2(p), hm2(p), y2(p+32), hm2(p+32)} = 32KB
#define TILE_U4 (64*32)        // 2048 uint4

// B smem: 2 tiles (64KB) + cw (2048 uint4 = 32KB) = 96KB
#define SMEM_BYTES ((2*TILE_U4 + 2048)*16)

// Scratch (device globals; no allocation)
__device__ uint4 g_pack2[(size_t)D_IN * 4 * TILE_U4];           // 33.5 MB
__device__ float g_partial[(size_t)NCHUNK * BATCH * D_OUT];     // 16 MB

// ---------------------------------------------------------------------------
// PCHIP helpers (branch-free)
// ---------------------------------------------------------------------------
__device__ __forceinline__ float pchip_interior(float d0, float d1) {
    float p   = d0 * d1;
    float den = d0 + d1;
    float m   = __fdividef(2.0f * p, den);
    bool  ok  = (p > 0.0f) && (fabsf(den) >= 1e-12f);
    return ok ? m : 0.0f;
}
__device__ __forceinline__ float pchip_endpoint(float d_near, float d_far) {
    float m = 1.5f * d_near - 0.5f * d_far;
    m = (m * d_near <= 0.0f) ? 0.0f : m;
    bool clamp3 = (d_near * d_far < 0.0f) && (fabsf(m) > 3.0f * fabsf(d_near));
    return clamp3 ? 3.0f * d_near : m;
}

// 4 records (knots jb..jb+3) for one spline. rowd points at y[jb] in smem
// (data at offset +1 within a 69-float pitch row, so rowd[-1] is valid).
__device__ __forceinline__ void spline4(const float* __restrict__ rowd, int jb,
                                        unsigned y2[4], unsigned h2[4]) {
    float ly[7];
#pragma unroll
    for (int k = 0; k < 7; ++k) ly[k] = rowd[k - 1];   // y[jb-1 .. jb+5]

    float d[6];
#pragma unroll
    for (int k = 0; k < 6; ++k) d[k] = (ly[k + 1] - ly[k]) * INV_H;

    float s[5];
#pragma unroll
    for (int k = 0; k < 5; ++k) s[k] = pchip_interior(d[k], d[k + 1]);
    if (jb == 0)  s[0] = pchip_endpoint(d[1], d[2]);   // m0
    if (jb == 60) s[3] = pchip_endpoint(d[3], d[2]);   // m63 (record 63 never gathered)

#pragma unroll
    for (int kk = 0; kk < 4; ++kk) {
        __half2 yv = __floats2half2_rn(ly[kk + 1], ly[kk + 2]);
        __half2 hv = __floats2half2_rn(H_VAL * s[kk], H_VAL * s[kk + 1]);
        y2[kk] = *reinterpret_cast<unsigned*>(&yv);
        h2[kk] = *reinterpret_cast<unsigned*>(&hv);
    }
}

// ---------------------------------------------------------------------------
// Kernel A: PCHIP + pack. Grid = 1024 groups x 2 halves, 256 threads.
// ---------------------------------------------------------------------------
__global__ void __launch_bounds__(256) pchip_pack_kernel(const float* __restrict__ y) {
    __shared__ float sy[32 * 69];                  // [staged row][1 + knot]

    const int t  = threadIdx.x;
    const int bx = blockIdx.x >> 1;                // din*4 + dxt
    const int ph = blockIdx.x & 1;                 // pair half

    const float* src = y + (size_t)bx * 4096;
#pragma unroll
    for (int f = t; f < 512; f += 256) {           // float4 index
        int r    = f >> 4;
        int col  = (f & 15) << 2;
        int spl  = ph * 16 + ((r < 16) ? r : (r + 16));
        float4 v = *(const float4*)(src + spl * KNOTS + col);
        float* dp = sy + r * 69 + 1 + col;
        dp[0] = v.x; dp[1] = v.y; dp[2] = v.z; dp[3] = v.w;
    }
    __syncthreads();

    const int i  = t & 15;
    const int q  = t >> 4;
    const int jb = q << 2;                         // 0..60

    unsigned ya[4], hA[4], yb[4], hB[4];
    spline4(sy + i * 69 + 1 + jb,        jb, ya, hA);   // spline ph*16+i
    spline4(sy + (i + 16) * 69 + 1 + jb, jb, yb, hB);   // spline ph*16+i+32

    uint4* dst = g_pack2 + (size_t)bx * TILE_U4 + jb * 32 + (ph * 16 + i);
#pragma unroll
    for (int kk = 0; kk < 4; ++kk) {
        uint4 rec;
        rec.x = ya[kk]; rec.y = hA[kk]; rec.z = yb[kk]; rec.w = hB[kk];
        dst[kk * 32] = rec;
    }
}

// ---------------------------------------------------------------------------
// Kernel B: main gather-accumulate.
// Grid (4 dxt, 2 by, 32 ch) = 256 blocks, 256 threads, 2 blocks/SM.
// Warp w owns b rows [w*32, w*32+32); lane l owns douts l and l+32 (local).
// Inner loop: explicit 2-deep pipeline — next broadcast+gather issued before
// current math, breaking the LDS->LDS->FMA serial chain.
// ---------------------------------------------------------------------------
__device__ __forceinline__ void cp_async16(void* dst, const void* src) {
    unsigned sa = (unsigned)__cvta_generic_to_shared(dst);
    asm volatile("cp.async.cg.shared.global [%0], [%1], 16;\n" :: "r"(sa), "l"(src));
}
__device__ __forceinline__ __half2 u2h(unsigned u) {
    return *reinterpret_cast<__half2*>(&u);
}

__global__ void __launch_bounds__(256, 2) kan_main_kernel(const float* __restrict__ x) {
    extern __shared__ uint4 sm4[];
    uint4* tile = sm4;                       // 2 x TILE_U4
    uint4* cw   = sm4 + 2 * TILE_U4;         // 2048: {wy, wh, byteoff, 0}

    const int dx  = blockIdx.x;   // dout tile of 64 (0..3)
    const int by  = blockIdx.y;   // b tile (0..1)
    const int ch  = blockIdx.z;   // din chunk (0..31)
    const int tid = threadIdx.x;

    // ---- hermite weights + gather byte offset ----
    for (int i = tid; i < TB * DCHUNK; i += 256) {
        int bb = i >> 3, dl = i & 7;
        float xv = x[(by * TB + bb) * D_IN + ch * DCHUNK + dl];
        xv = fminf(fmaxf(xv, -2.0f), 2.0f);
        float tt = (xv + 2.0f) * INV_H;
        int idx = (int)floorf(tt);
        if (idx > KNOTS - 2) idx = KNOTS - 2;
        if (idx < 0) idx = 0;
        float u  = tt - (float)idx;
        float u2 = u * u, u3 = u2 * u;
        float h00 = 2.0f * u3 - 3.0f * u2 + 1.0f;
        float h10 = u3 - 2.0f * u2 + u;
        float h01 = 3.0f * u2 - 2.0f * u3;
        float h11 = u3 - u2;
        __half2 wy = __floats2half2_rn(h00, h01);
        __half2 wh = __floats2half2_rn(h10, h11);
        uint4 r;
        r.x = *reinterpret_cast<unsigned*>(&wy);
        r.y = *reinterpret_cast<unsigned*>(&wh);
        r.z = (unsigned)(idx << 9);          // idx * 512B (row = 32 uint4)
        r.w = 0;
        cw[i] = r;
    }

    const int w = tid >> 5, l = tid & 31;
    float acc0[32], acc1[32];
#pragma unroll
    for (int bb = 0; bb < 32; ++bb) { acc0[bb] = 0.0f; acc1[bb] = 0.0f; }

    auto issue_copy = [&](int d, int st) {
        const uint4* src = g_pack2 + ((size_t)(ch * DCHUNK + d) * 4 + dx) * TILE_U4;
        uint4* dst = tile + st * TILE_U4;
#pragma unroll
        for (int j = tid; j < TILE_U4; j += 256) cp_async16(dst + j, src + j);
    };

    issue_copy(0, 0);
    asm volatile("cp.async.commit_group;\n" ::: "memory");

    for (int d = 0; d < DCHUNK; ++d) {
        const int st = d & 1;
        if (d < DCHUNK - 1) {
            issue_copy(d + 1, st ^ 1);
            asm volatile("cp.async.commit_group;\n" ::: "memory");
            asm volatile("cp.async.wait_group 1;\n" ::: "memory");
        } else {
            asm volatile("cp.async.wait_group 0;\n" ::: "memory");
        }
        __syncthreads();

        const char* tb = (const char*)(tile + st * TILE_U4) + (l << 4);
        const int base = (w * 32) * DCHUNK + d;

        // 2-deep software pipeline over bb
        uint4 r0 = cw[base];
        uint4 g0 = *(const uint4*)(tb + r0.z);
#pragma unroll
        for (int bb = 0; bb < 32; ++bb) {
            uint4 r1, g1;
            if (bb < 31) {
                r1 = cw[base + (bb + 1) * DCHUNK];     // next broadcast
                g1 = *(const uint4*)(tb + r1.z);       // next gather (in flight)
            }
            __half2 p0 = __hfma2(u2h(r0.y), u2h(g0.y), __hmul2(u2h(r0.x), u2h(g0.x)));
            __half2 p1 = __hfma2(u2h(r0.y), u2h(g0.w), __hmul2(u2h(r0.x), u2h(g0.z)));
            acc0[bb] += __half2float(__hadd(__low2half(p0), __high2half(p0)));
            acc1[bb] += __half2float(__hadd(__low2half(p1), __high2half(p1)));
            r0 = r1; g0 = g1;
        }
        __syncthreads();
    }

    // ---- write partials ----
    float* P = g_partial + ((size_t)ch * BATCH + by * TB + w * 32) * D_OUT + dx * 64;
#pragma unroll
    for (int bb = 0; bb < 32; ++bb) {
        P[bb * D_OUT + l]      = acc0[bb];
        P[bb * D_OUT + l + 32] = acc1[bb];
    }
}

// ---------------------------------------------------------------------------
// Kernel C: reduce 32 partials + bias
// ---------------------------------------------------------------------------
__global__ void __launch_bounds__(256) reduce_kernel(
        const float* __restrict__ bias, float* __restrict__ out) {
    int i = blockIdx.x * 256 + threadIdx.x;            // float4 index
    const float4* P = (const float4*)g_partial;
    float4 s = ((const float4*)bias)[i & 63];
#pragma unroll
    for (int c = 0; c < NCHUNK; ++c) {
        float4 p = P[(size_t)c * (BATCH * D_OUT / 4) + i];
        s.x += p.x; s.y += p.y; s.z += p.z; s.w += p.w;
    }
    ((float4*)out)[i] = s;
}

// ---------------------------------------------------------------------------
extern "C" void kernel_launch(void* const* d_in, const int* in_sizes, int n_in,
                              void* d_out, int out_size) {
    const float* x    = (const float*)d_in[0];
    const float* y    = (const float*)d_in[1];
    const float* bias = (const float*)d_in[2];
    float* out = (float*)d_out;

    cudaFuncSetAttribute(kan_main_kernel,
                         cudaFuncAttributeMaxDynamicSharedMemorySize, SMEM_BYTES);

    pchip_pack_kernel<<<D_IN * 4 * 2, 256>>>(y);
    kan_main_kernel<<<dim3(4, 2, NCHUNK), 256, SMEM_BYTES>>>(x);
    reduce_kernel<<<(BATCH * D_OUT / 4) / 256, 256>>>(bias, out);
}

// round 10
// speedup vs baseline: 1.7859x; 1.0645x over previous
#include <cuda_runtime.h>
#include <cuda_fp16.h>
#include <cstdint>

// Problem constants
#define D_IN   256
#define D_OUT  256
#define BATCH  512
#define KNOTS  64
#define INV_H  15.75f          // 63/4, exact in fp32
#define H_VAL  (4.0f/63.0f)

#define NCHUNK 32              // din chunks
#define DCHUNK 8               // din per chunk
#define TB     256             // batch rows per block

// B tile: 64 knots x 32 pairs of uint4 {y2(p), hm2(p), y2(p+32), hm2(p+32)} = 32KB
#define TILE_U4   (64*32)      // 2048 uint4
#define TILE_BYTES (TILE_U4*16)

// B smem bytes: 2 tiles (64KB) + cw (32KB) + 2 mbarriers (16B, padded)
#define OFF_CW    (2*TILE_BYTES)
#define OFF_MBAR  (OFF_CW + 2048*16)
#define SMEM_BYTES (OFF_MBAR + 64)

// Scratch (device globals; no allocation)
__device__ uint4 g_pack2[(size_t)D_IN * 4 * TILE_U4];           // 33.5 MB

// ---------------------------------------------------------------------------
// PCHIP helpers (branch-free)
// ---------------------------------------------------------------------------
__device__ __forceinline__ float pchip_interior(float d0, float d1) {
    float p   = d0 * d1;
    float den = d0 + d1;
    float m   = __fdividef(2.0f * p, den);
    bool  ok  = (p > 0.0f) && (fabsf(den) >= 1e-12f);
    return ok ? m : 0.0f;
}
__device__ __forceinline__ float pchip_endpoint(float d_near, float d_far) {
    float m = 1.5f * d_near - 0.5f * d_far;
    m = (m * d_near <= 0.0f) ? 0.0f : m;
    bool clamp3 = (d_near * d_far < 0.0f) && (fabsf(m) > 3.0f * fabsf(d_near));
    return clamp3 ? 3.0f * d_near : m;
}

// 4 records (knots jb..jb+3) for one spline. rowd points at y[jb] in smem
// (data at offset +1 within a 69-float pitch row, so rowd[-1] is valid).
__device__ __forceinline__ void spline4(const float* __restrict__ rowd, int jb,
                                        unsigned y2[4], unsigned h2[4]) {
    float ly[7];
#pragma unroll
    for (int k = 0; k < 7; ++k) ly[k] = rowd[k - 1];   // y[jb-1 .. jb+5]

    float d[6];
#pragma unroll
    for (int k = 0; k < 6; ++k) d[k] = (ly[k + 1] - ly[k]) * INV_H;

    float s[5];
#pragma unroll
    for (int k = 0; k < 5; ++k) s[k] = pchip_interior(d[k], d[k + 1]);
    if (jb == 0)  s[0] = pchip_endpoint(d[1], d[2]);   // m0
    if (jb == 60) s[3] = pchip_endpoint(d[3], d[2]);   // m63 (record 63 never gathered)

#pragma unroll
    for (int kk = 0; kk < 4; ++kk) {
        __half2 yv = __floats2half2_rn(ly[kk + 1], ly[kk + 2]);
        __half2 hv = __floats2half2_rn(H_VAL * s[kk], H_VAL * s[kk + 1]);
        y2[kk] = *reinterpret_cast<unsigned*>(&yv);
        h2[kk] = *reinterpret_cast<unsigned*>(&hv);
    }
}

// ---------------------------------------------------------------------------
// Kernel A: PCHIP + pack. Grid = 1024 groups x 2 halves, 256 threads.
// ---------------------------------------------------------------------------
__global__ void __launch_bounds__(256) pchip_pack_kernel(const float* __restrict__ y) {
    __shared__ float sy[32 * 69];                  // [staged row][1 + knot]

    const int t  = threadIdx.x;
    const int bx = blockIdx.x >> 1;                // din*4 + dxt
    const int ph = blockIdx.x & 1;                 // pair half

    const float* src = y + (size_t)bx * 4096;
#pragma unroll
    for (int f = t; f < 512; f += 256) {           // float4 index
        int r    = f >> 4;
        int col  = (f & 15) << 2;
        int spl  = ph * 16 + ((r < 16) ? r : (r + 16));
        float4 v = *(const float4*)(src + spl * KNOTS + col);
        float* dp = sy + r * 69 + 1 + col;
        dp[0] = v.x; dp[1] = v.y; dp[2] = v.z; dp[3] = v.w;
    }
    __syncthreads();

    const int i  = t & 15;
    const int q  = t >> 4;
    const int jb = q << 2;                         // 0..60

    unsigned ya[4], hA[4], yb[4], hB[4];
    spline4(sy + i * 69 + 1 + jb,        jb, ya, hA);   // spline ph*16+i
    spline4(sy + (i + 16) * 69 + 1 + jb, jb, yb, hB);   // spline ph*16+i+32

    uint4* dst = g_pack2 + (size_t)bx * TILE_U4 + jb * 32 + (ph * 16 + i);
#pragma unroll
    for (int kk = 0; kk < 4; ++kk) {
        uint4 rec;
        rec.x = ya[kk]; rec.y = hA[kk]; rec.z = yb[kk]; rec.w = hB[kk];
        dst[kk * 32] = rec;
    }
}

// ---------------------------------------------------------------------------
// Kernel I: out = bias (broadcast init; B atomically accumulates on top)
// ---------------------------------------------------------------------------
__global__ void __launch_bounds__(256) init_out_kernel(
        const float* __restrict__ bias, float* __restrict__ out) {
    int i = blockIdx.x * 256 + threadIdx.x;            // float4 index
    ((float4*)out)[i] = ((const float4*)bias)[i & 63];
}

// ---------------------------------------------------------------------------
// Kernel B: main gather-accumulate.
// Grid (4 dxt, 2 by, 32 ch) = 256 blocks, 256 threads, 2 blocks/SM.
// Tile fills via cp.async.bulk (TMA pipe, mbarrier complete_tx) — LSU only
// does gathers + broadcasts. Epilogue: coalesced atomicAdd into out.
// ---------------------------------------------------------------------------
__device__ __forceinline__ __half2 u2h(unsigned u) {
    return *reinterpret_cast<__half2*>(&u);
}
__device__ __forceinline__ void mbar_init(unsigned mbar, unsigned count) {
    asm volatile("mbarrier.init.shared.b64 [%0], %1;" :: "r"(mbar), "r"(count) : "memory");
}
__device__ __forceinline__ void mbar_expect_tx(unsigned mbar, unsigned tx) {
    asm volatile("mbarrier.arrive.expect_tx.shared.b64 _, [%0], %1;"
                 :: "r"(mbar), "r"(tx) : "memory");
}
__device__ __forceinline__ void bulk_copy(unsigned dst_smem, const void* src, unsigned bytes,
                                          unsigned mbar) {
    asm volatile("cp.async.bulk.shared::cta.global.mbarrier::complete_tx::bytes "
                 "[%0], [%1], %2, [%3];"
                 :: "r"(dst_smem), "l"(src), "r"(bytes), "r"(mbar) : "memory");
}
__device__ __forceinline__ void mbar_wait(unsigned mbar, unsigned parity) {
    unsigned done;
    asm volatile("{\n\t.reg .pred p;\n\t"
                 "mbarrier.try_wait.parity.acquire.cta.shared::cta.b64 p, [%1], %2;\n\t"
                 "selp.b32 %0, 1, 0, p;\n\t}"
                 : "=r"(done) : "r"(mbar), "r"(parity) : "memory");
    if (!done) {
        asm volatile("{\n\t.reg .pred P1;\n\t"
                     "WAIT_LOOP_%=:\n\t"
                     "mbarrier.try_wait.parity.acquire.cta.shared::cta.b64 P1, [%0], %1, 0x989680;\n\t"
                     "@P1 bra.uni WAIT_DONE_%=;\n\t"
                     "bra.uni WAIT_LOOP_%=;\n\t"
                     "WAIT_DONE_%=:\n\t}"
                     :: "r"(mbar), "r"(parity) : "memory");
    }
}

__global__ void __launch_bounds__(256, 2) kan_main_kernel(
        const float* __restrict__ x, float* __restrict__ out) {
    extern __shared__ char smem[];
    uint4*   tile  = (uint4*)smem;                    // 2 x TILE_U4
    uint4*   cw    = (uint4*)(smem + OFF_CW);         // 2048: {wy, wh, byteoff, 0}
    unsigned smem_base;
    asm("{ .reg .u64 t; cvta.to.shared.u64 t, %1; cvt.u32.u64 %0, t; }"
        : "=r"(smem_base) : "l"(smem));
    const unsigned mbar0 = smem_base + OFF_MBAR;
    const unsigned mbar1 = smem_base + OFF_MBAR + 8;

    const int dx  = blockIdx.x;   // dout tile of 64 (0..3)
    const int by  = blockIdx.y;   // b tile (0..1)
    const int ch  = blockIdx.z;   // din chunk (0..31)
    const int tid = threadIdx.x;

    if (tid == 0) {
        mbar_init(mbar0, 1);
        mbar_init(mbar1, 1);
    }

    // ---- hermite weights + gather byte offset ----
    for (int i = tid; i < TB * DCHUNK; i += 256) {
        int bb = i >> 3, dl = i & 7;
        float xv = x[(by * TB + bb) * D_IN + ch * DCHUNK + dl];
        xv = fminf(fmaxf(xv, -2.0f), 2.0f);
        float tt = (xv + 2.0f) * INV_H;
        int idx = (int)floorf(tt);
        if (idx > KNOTS - 2) idx = KNOTS - 2;
        if (idx < 0) idx = 0;
        float u  = tt - (float)idx;
        float u2 = u * u, u3 = u2 * u;
        float h00 = 2.0f * u3 - 3.0f * u2 + 1.0f;
        float h10 = u3 - 2.0f * u2 + u;
        float h01 = 3.0f * u2 - 2.0f * u3;
        float h11 = u3 - u2;
        __half2 wy = __floats2half2_rn(h00, h01);
        __half2 wh = __floats2half2_rn(h10, h11);
        uint4 r;
        r.x = *reinterpret_cast<unsigned*>(&wy);
        r.y = *reinterpret_cast<unsigned*>(&wh);
        r.z = (unsigned)(idx << 9);          // idx * 512B (row = 32 uint4)
        r.w = 0;
        cw[i] = r;
    }
    __syncthreads();                         // mbarriers initialized + cw visible ordering

    const int w = tid >> 5, l = tid & 31;
    float acc0[32], acc1[32];
#pragma unroll
    for (int bb = 0; bb < 32; ++bb) { acc0[bb] = 0.0f; acc1[bb] = 0.0f; }

    const uint4* gsrc = g_pack2 + ((size_t)ch * DCHUNK * 4 + dx) * TILE_U4;

    auto issue_copy = [&](int d, int st) {
        if (tid == 0) {
            unsigned mb = st ? mbar1 : mbar0;
            mbar_expect_tx(mb, TILE_BYTES);
            bulk_copy(smem_base + st * TILE_BYTES, gsrc + (size_t)d * 4 * TILE_U4,
                      TILE_BYTES, mb);
        }
    };

    issue_copy(0, 0);

    int phase0 = 0, phase1 = 0;

    for (int d = 0; d < DCHUNK; ++d) {
        const int st = d & 1;
        if (d < DCHUNK - 1) issue_copy(d + 1, st ^ 1);

        // wait for this stage's tile
        if (st == 0) { mbar_wait(mbar0, phase0); phase0 ^= 1; }
        else         { mbar_wait(mbar1, phase1); phase1 ^= 1; }

        const char* tb = (const char*)(tile + st * TILE_U4) + (l << 4);
        const int base = (w * 32) * DCHUNK + d;

        // software pipeline: records 2 ahead, gathers 1 ahead
        uint4 rA = cw[base];
        uint4 rB = cw[base + DCHUNK];
        uint4 gA = *(const uint4*)(tb + rA.z);
#pragma unroll
        for (int bb = 0; bb < 32; ++bb) {
            uint4 rC, gB;
            if (bb < 30) rC = cw[base + (bb + 2) * DCHUNK];
            if (bb < 31) gB = *(const uint4*)(tb + rB.z);

            __half2 p0 = __hfma2(u2h(rA.y), u2h(gA.y), __hmul2(u2h(rA.x), u2h(gA.x)));
            __half2 p1 = __hfma2(u2h(rA.y), u2h(gA.w), __hmul2(u2h(rA.x), u2h(gA.z)));
            acc0[bb] += __half2float(__hadd(__low2half(p0), __high2half(p0)));
            acc1[bb] += __half2float(__hadd(__low2half(p1), __high2half(p1)));

            rA = rB; rB = rC; gA = gB;
        }
        __syncthreads();   // all reads of tile[st] done before it is refilled at d+2
    }

    // ---- atomic accumulate into out (coalesced per warp) ----
    float* O = out + ((size_t)by * TB + w * 32) * D_OUT + dx * 64;
#pragma unroll
    for (int bb = 0; bb < 32; ++bb) {
        atomicAdd(O + bb * D_OUT + l,      acc0[bb]);
        atomicAdd(O + bb * D_OUT + l + 32, acc1[bb]);
    }
}

// ---------------------------------------------------------------------------
extern "C" void kernel_launch(void* const* d_in, const int* in_sizes, int n_in,
                              void* d_out, int out_size) {
    const float* x    = (const float*)d_in[0];
    const float* y    = (const float*)d_in[1];
    const float* bias = (const float*)d_in[2];
    float* out = (float*)d_out;

    cudaFuncSetAttribute(kan_main_kernel,
                         cudaFuncAttributeMaxDynamicSharedMemorySize, SMEM_BYTES);

    pchip_pack_kernel<<<D_IN * 4 * 2, 256>>>(y);
    init_out_kernel<<<(BATCH * D_OUT / 4) / 256, 256>>>(bias, out);
    kan_main_kernel<<<dim3(4, 2, NCHUNK), 256, SMEM_BYTES>>>(x, out);
}